// round 15
// baseline (speedup 1.0000x reference)
#include <cuda_runtime.h>
#include <cuda_fp16.h>
#include <cstdint>
#include <cstddef>

#define MAXN 100000
#define MPAD 100096
#define NI   1024

#define BM   128
#define BN   128
#define BK   64
#define NCH  (NI / BK)          // 16
#define NSTG 2

// smem tile: [128 rows][72 fp16] (64 data + 8 pad) = 18432 B
#define ROW_B    144
#define TILE_B   (128 * ROW_B)         // 18432
#define OFF_A    0
#define OFF_B    (1 * TILE_B)
#define STAGE_B  (2 * TILE_B)          // 36864
#define DYN_SMEM (NSTG * STAGE_B)      // 73728

// ---------------------------------------------------------------- scratch
// per-chain activation buffers; FOUR weight buffers (w1_0, w1_1, w2_0, w2_1).
__device__ __half g_Xh [2][(size_t)MPAD * NI];  // zero-init: rows >= M stay 0
__device__ __half g_Wh [4][(size_t)NI * NI];
__device__ float  g_bufH[2][(size_t)MPAD * NI];

// ---------------------------------------------------------------- PTX utils
__device__ __forceinline__ uint32_t smem_u32(const void* p)
{
    uint32_t a;
    asm("{ .reg .u64 t; cvta.to.shared.u64 t, %1; cvt.u32.u64 %0, t; }"
        : "=r"(a) : "l"(p));
    return a;
}

#define LDSM_X4(r, addr)                                                        \
    asm volatile("ldmatrix.sync.aligned.m8n8.x4.shared.b16 {%0,%1,%2,%3}, [%4];"\
        : "=r"((r)[0]), "=r"((r)[1]), "=r"((r)[2]), "=r"((r)[3]) : "r"(addr))

__device__ __forceinline__ void mma_f16(float* c, const uint32_t* a,
                                        const uint32_t b0, const uint32_t b1)
{
    asm volatile(
        "mma.sync.aligned.m16n8k16.row.col.f32.f16.f16.f32 "
        "{%0,%1,%2,%3}, {%4,%5,%6,%7}, {%8,%9}, {%0,%1,%2,%3};\n"
        : "+f"(c[0]), "+f"(c[1]), "+f"(c[2]), "+f"(c[3])
        : "r"(a[0]), "r"(a[1]), "r"(a[2]), "r"(a[3]), "r"(b0), "r"(b1));
}

// ---------------------------------------------------------------- 256-thr stats
__device__ __forceinline__ void stats256(float s1, float s2, float* red,
                                         float& mu, float& rstd)
{
    #pragma unroll
    for (int off = 16; off > 0; off >>= 1) {
        s1 += __shfl_xor_sync(0xffffffffu, s1, off);
        s2 += __shfl_xor_sync(0xffffffffu, s2, off);
    }
    int wid = threadIdx.x >> 5, lane = threadIdx.x & 31;
    if (lane == 0) { red[wid] = s1; red[8 + wid] = s2; }
    __syncthreads();
    if (wid == 0) {
        s1 = (lane < 8) ? red[lane] : 0.f;
        s2 = (lane < 8) ? red[8 + lane] : 0.f;
        #pragma unroll
        for (int off = 4; off > 0; off >>= 1) {
            s1 += __shfl_xor_sync(0xffffffffu, s1, off);
            s2 += __shfl_xor_sync(0xffffffffu, s2, off);
        }
        if (lane == 0) { red[0] = s1; red[8] = s2; }
    }
    __syncthreads();
    mu   = red[0] * (1.0f / NI);
    float var = red[8] * (1.0f / NI) - mu * mu;
    rstd = rsqrtf(var + 1e-5f);
}

// ---------------------------------------------------------------- stage 1
// Gram + sign-clamp + LN1 + lrelu -> fp16; 256 threads x 4 entries
__global__ void prep_kernel(const float* __restrict__ f,
                            const float* __restrict__ gamma,
                            const float* __restrict__ beta,
                            int m, int which)
{
    __half* __restrict__ Xh = g_Xh[which];
    int n = blockIdx.x;
    __shared__ float sv[96];
    __shared__ float red[16];
    int t = threadIdx.x;                       // 0..255
    if (t < 32 * m) sv[t] = f[(size_t)n * 32 * m + t];
    __syncthreads();

    const int a  = t >> 3;                     // row (0..31)
    const int b0 = (t & 7) * 4;                // first col of 4
    float y[4];
    #pragma unroll
    for (int i = 0; i < 4; ++i) {
        float d = 0.f;
        #pragma unroll 3
        for (int c = 0; c < m; ++c) d += sv[a * m + c] * sv[(b0 + i) * m + c];
        if (d > 0.f)      d = fmaxf(d,  1e-12f);
        else if (d < 0.f) d = fminf(d, -1e-12f);
        y[i] = d;
    }
    float s1 = y[0] + y[1] + y[2] + y[3];
    float s2 = y[0]*y[0] + y[1]*y[1] + y[2]*y[2] + y[3]*y[3];
    float mu, rstd;
    stats256(s1, s2, red, mu, rstd);

    size_t base = (size_t)n * NI + t * 4;
    const float4 gg = *(const float4*)&gamma[t * 4];
    const float4 bb = *(const float4*)&beta[t * 4];
    float v0 = (y[0]-mu)*rstd*gg.x + bb.x; v0 = (v0>=0.f)?v0:0.01f*v0;
    float v1 = (y[1]-mu)*rstd*gg.y + bb.y; v1 = (v1>=0.f)?v1:0.01f*v1;
    float v2 = (y[2]-mu)*rstd*gg.z + bb.z; v2 = (v2>=0.f)?v2:0.01f*v2;
    float v3 = (y[3]-mu)*rstd*gg.w + bb.w; v3 = (v3>=0.f)?v3:0.01f*v3;
    *(__half2*)&Xh[base]     = __halves2half2(__float2half_rn(v0), __float2half_rn(v1));
    *(__half2*)&Xh[base + 2] = __halves2half2(__float2half_rn(v2), __float2half_rn(v3));
}

// ---------------------------------------------------------------- stage 3
// LN2 + lrelu -> fp16; 256 threads x float4
__global__ void mid_ln_kernel(const float* __restrict__ gamma,
                              const float* __restrict__ beta,
                              int which)
{
    const float* __restrict__ H  = g_bufH[which];
    __half* __restrict__      Xh = g_Xh[which];
    int n = blockIdx.x;
    int t = threadIdx.x;
    __shared__ float red[16];
    const float4 d = *(const float4*)&H[(size_t)n * NI + t * 4];

    float s1 = d.x + d.y + d.z + d.w;
    float s2 = d.x*d.x + d.y*d.y + d.z*d.z + d.w*d.w;
    float mu, rstd;
    stats256(s1, s2, red, mu, rstd);

    const float4 gg = *(const float4*)&gamma[t * 4];
    const float4 bb = *(const float4*)&beta[t * 4];
    float y0 = (d.x-mu)*rstd*gg.x + bb.x; y0 = (y0>=0.f)?y0:0.01f*y0;
    float y1 = (d.y-mu)*rstd*gg.y + bb.y; y1 = (y1>=0.f)?y1:0.01f*y1;
    float y2 = (d.z-mu)*rstd*gg.z + bb.z; y2 = (y2>=0.f)?y2:0.01f*y2;
    float y3 = (d.w-mu)*rstd*gg.w + bb.w; y3 = (y3>=0.f)?y3:0.01f*y3;

    size_t base = (size_t)n * NI + t * 4;
    *(__half2*)&Xh[base]     = __halves2half2(__float2half_rn(y0), __float2half_rn(y1));
    *(__half2*)&Xh[base + 2] = __halves2half2(__float2half_rn(y2), __float2half_rn(y3));
}

// ---------------------------------------------------------------- W -> fp16
__global__ void wsplit_kernel(const float* __restrict__ W, int wbuf)
{
    int i = blockIdx.x * 256 + threadIdx.x;
    g_Wh[wbuf][i] = __float2half_rn(W[i]);
}

// ---------------------------------------------------------------- GEMM
// C[M,1024] = X @ W^T (+bias): fp16 HMMA m16n8k16.
// 128x128x64 tile, 8 warps (warp 64x32), 2-stage cp.async pipeline.
__device__ __forceinline__ void load_stage(uint32_t sbase,
                                           const __half* __restrict__ Xh,
                                           const __half* __restrict__ Wh,
                                           int bm, int bn, int k0, int tid)
{
    #pragma unroll 8
    for (int i = 0; i < 8; ++i) {
        int idx  = tid + i * 256;          // 0..2047
        int tile = idx >> 10;              // 0..1
        int r    = (idx >> 3) & 127;
        int c    = (idx & 7) * 8;          // fp16 col
        const __half* src = (tile == 0)
            ? Xh + (size_t)(bm + r) * NI + k0 + c
            : Wh + (size_t)(bn + r) * NI + k0 + c;
        uint32_t dst = sbase + tile * TILE_B + r * ROW_B + c * 2;
        asm volatile("cp.async.cg.shared.global [%0], [%1], 16;"
                     :: "r"(dst), "l"(src) : "memory");
    }
    asm volatile("cp.async.commit_group;" ::: "memory");
}

__global__ __launch_bounds__(256)
void gemm_f16_kernel(const float* __restrict__ bias, int M, int which, int wbuf)
{
    extern __shared__ __align__(128) char dyn[];
    const __half* __restrict__ Xh = g_Xh[which];
    const __half* __restrict__ Wh = g_Wh[wbuf];
    float* __restrict__        H  = g_bufH[which];

    const int tid    = threadIdx.x;
    const int wid    = tid >> 5;
    const int lane   = tid & 31;
    const int warp_m = wid >> 2;           // 0..1
    const int warp_n = wid & 3;            // 0..3
    const int bn     = blockIdx.x * BN;
    const int bm     = blockIdx.y * BM;

    const uint32_t sdyn = smem_u32(dyn);

    const uint32_t laneA = (uint32_t)((lane & 15) * ROW_B + (lane >> 4) * 16);
    const uint32_t laneB = (uint32_t)(((lane & 7) + ((lane >> 4) * 8)) * ROW_B
                                      + (((lane >> 3) & 1) * 16));
    const uint32_t aWarp = (uint32_t)(warp_m * 64 * ROW_B);
    const uint32_t bWarp = (uint32_t)(warp_n * 32 * ROW_B);

    float acc[4][4][4];
    #pragma unroll
    for (int i = 0; i < 4; ++i)
        #pragma unroll
        for (int j = 0; j < 4; ++j)
            #pragma unroll
            for (int k = 0; k < 4; ++k) acc[i][j][k] = 0.f;

    load_stage(sdyn + 0 * STAGE_B, Xh, Wh, bm, bn, 0 * BK, tid);
    load_stage(sdyn + 1 * STAGE_B, Xh, Wh, bm, bn, 1 * BK, tid);

    for (int c = 0; c < NCH; ++c) {
        asm volatile("cp.async.wait_group 1;" ::: "memory");
        __syncthreads();
        const uint32_t sb = sdyn + (c & 1) * STAGE_B;

        #pragma unroll
        for (int kg = 0; kg < 4; ++kg) {
            const uint32_t kb = kg * 32;     // 16 fp16 = 32 B
            uint32_t ah[4][4], bh[2][4];
            #pragma unroll
            for (int mt = 0; mt < 4; ++mt) {
                uint32_t o = aWarp + mt * (16 * ROW_B) + laneA + kb;
                LDSM_X4(ah[mt], sb + OFF_A + o);
            }
            #pragma unroll
            for (int n2 = 0; n2 < 2; ++n2) {
                uint32_t o = bWarp + n2 * (16 * ROW_B) + laneB + kb;
                LDSM_X4(bh[n2], sb + OFF_B + o);
            }
            #pragma unroll
            for (int mt = 0; mt < 4; ++mt)
                #pragma unroll
                for (int nt = 0; nt < 4; ++nt) {
                    const int n2 = nt >> 1, ns = (nt & 1) * 2;
                    mma_f16(acc[mt][nt], ah[mt], bh[n2][ns], bh[n2][ns + 1]);
                }
        }
        __syncthreads();
        if (c + NSTG < NCH)
            load_stage(sb, Xh, Wh, bm, bn, (c + NSTG) * BK, tid);
    }

    // ---- epilogue: direct stores
    const int g  = lane >> 2;
    const int tg = lane & 3;
    #pragma unroll
    for (int mt = 0; mt < 4; ++mt) {
        int row0 = bm + warp_m * 64 + mt * 16 + g;
        #pragma unroll
        for (int nt = 0; nt < 4; ++nt) {
            int col = bn + warp_n * 32 + nt * 8 + tg * 2;
            float b0 = bias ? __ldg(&bias[col])     : 0.f;
            float b1 = bias ? __ldg(&bias[col + 1]) : 0.f;
            if (row0 < M) {
                float2 v = make_float2(acc[mt][nt][0] + b0, acc[mt][nt][1] + b1);
                *(float2*)&H[(size_t)row0 * NI + col] = v;
            }
            if (row0 + 8 < M) {
                float2 v = make_float2(acc[mt][nt][2] + b0, acc[mt][nt][3] + b1);
                *(float2*)&H[(size_t)(row0 + 8) * NI + col] = v;
            }
        }
    }
}

// ---------------------------------------------------------------- stage 5
// one warp = one node; lane = output channel. Serial register softmax.
__global__ void post_kernel(const float* __restrict__ f,
                            float* __restrict__ out,
                            int m, int N, int which)
{
    const float* __restrict__ H = g_bufH[which];
    __shared__ float sv[8][96];
    const int w    = threadIdx.x >> 5;           // warp in block (0..7)
    const int lane = threadIdx.x & 31;
    const int n    = blockIdx.x * 8 + w;
    if (n >= N) return;

    for (int i = lane; i < 32 * m; i += 32)
        sv[w][i] = f[(size_t)n * 32 * m + i];
    __syncwarp();

    float l[32];
    const float4* lp = (const float4*)&H[(size_t)n * NI + lane * 32];
    #pragma unroll
    for (int q = 0; q < 8; ++q) {
        float4 v4 = lp[q];
        l[q*4+0] = v4.x; l[q*4+1] = v4.y; l[q*4+2] = v4.z; l[q*4+3] = v4.w;
    }
    float mx = l[0];
    #pragma unroll
    for (int b = 1; b < 32; ++b) mx = fmaxf(mx, l[b]);
    float s = 0.f;
    #pragma unroll
    for (int b = 0; b < 32; ++b) { l[b] = __expf(l[b] - mx); s += l[b]; }
    float inv = 1.0f / s;

    #pragma unroll 3
    for (int c = 0; c < m; ++c) {
        float acc = 0.f;
        #pragma unroll
        for (int b = 0; b < 32; ++b) acc += l[b] * sv[w][b * m + c];
        out[((size_t)n * 32 + lane) * m + c] = acc * inv;
    }
}

// ---------------------------------------------------------------- launch
// Event-DAG schedule: all 4 GEMMs back-to-back on the capture stream; each
// chain's aux kernels run on side streams inside the OTHER GEMM's window.
// Weight buffers: 0=w1_0, 1=w1_1, 2=w2_0, 3=w2_1 (no aliasing).
extern "C" void kernel_launch(void* const* d_in, const int* in_sizes, int n_in,
                              void* d_out, int out_size)
{
    static cudaStream_t s2 = nullptr, s3 = nullptr;
    static cudaEvent_t  eFork, eW10, eW11, eW2, eP1, eG10, eG11, eG20, eG21,
                        eM0, eM1, ePost0, ePost1;
    if (!s2) {
        cudaStreamCreateWithFlags(&s2, cudaStreamNonBlocking);
        cudaStreamCreateWithFlags(&s3, cudaStreamNonBlocking);
        cudaEvent_t* evs[] = { &eFork, &eW10, &eW11, &eW2, &eP1, &eG10, &eG11,
                               &eG20, &eG21, &eM0, &eM1, &ePost0, &ePost1 };
        for (auto e : evs) cudaEventCreateWithFlags(e, cudaEventDisableTiming);
        cudaFuncSetAttribute(gemm_f16_kernel,
                             cudaFuncAttributeMaxDynamicSharedMemorySize, DYN_SMEM);
    }

    const float* f0 = (const float*)d_in[0];
    const float* f1 = (const float*)d_in[1];
    int N0 = in_sizes[0] / 32;
    int N1 = in_sizes[1] / 96;
    if (N0 > MAXN) N0 = MAXN;
    if (N1 > MAXN) N1 = MAXN;
    float* out0 = (float*)d_out;
    float* out1 = out0 + (size_t)N0 * 32;
    void* const* p0 = d_in + 2;
    void* const* p1 = d_in + 9;

    dim3 g0(NI / BN, (N0 + BM - 1) / BM);
    dim3 g1(NI / BN, (N1 + BM - 1) / BM);
    cudaStream_t s0 = (cudaStream_t)0;

    // fork
    cudaEventRecord(eFork, s0);
    cudaStreamWaitEvent(s2, eFork, 0);
    cudaStreamWaitEvent(s3, eFork, 0);

    // s3: w1_0 first (narrowest G1_0 dependency), then w1_1, then w2 splits
    wsplit_kernel<<<(NI * NI) / 256, 256, 0, s3>>>((const float*)p0[2], 0); // w1_0
    cudaEventRecord(eW10, s3);
    wsplit_kernel<<<(NI * NI) / 256, 256, 0, s3>>>((const float*)p1[2], 1); // w1_1
    cudaEventRecord(eW11, s3);
    wsplit_kernel<<<(NI * NI) / 256, 256, 0, s3>>>((const float*)p0[5], 2); // w2_0
    wsplit_kernel<<<(NI * NI) / 256, 256, 0, s3>>>((const float*)p1[5], 3); // w2_1
    cudaEventRecord(eW2, s3);

    // s2: chain1 prep
    prep_kernel<<<N1, 256, 0, s2>>>(f1, (const float*)p1[0], (const float*)p1[1], 3, 1);
    cudaEventRecord(eP1, s2);

    // s0: chain0 prep, then GEMM train
    prep_kernel<<<N0, 256, 0, s0>>>(f0, (const float*)p0[0], (const float*)p0[1], 1, 0);
    cudaStreamWaitEvent(s0, eW10, 0);
    gemm_f16_kernel<<<g0, 256, DYN_SMEM, s0>>>(nullptr, N0, 0, 0);          // G1_0
    cudaEventRecord(eG10, s0);
    cudaStreamWaitEvent(s0, eP1, 0);
    cudaStreamWaitEvent(s0, eW11, 0);
    gemm_f16_kernel<<<g1, 256, DYN_SMEM, s0>>>(nullptr, N1, 1, 1);          // G1_1
    cudaEventRecord(eG11, s0);

    // s3: mid0 under G1_1
    cudaStreamWaitEvent(s3, eG10, 0);
    mid_ln_kernel<<<N0, 256, 0, s3>>>((const float*)p0[3], (const float*)p0[4], 0);
    cudaEventRecord(eM0, s3);

    // s2: mid1 under G2_0
    cudaStreamWaitEvent(s2, eG11, 0);
    mid_ln_kernel<<<N1, 256, 0, s2>>>((const float*)p1[3], (const float*)p1[4], 1);
    cudaEventRecord(eM1, s2);

    // s0: G2_0, G2_1 (need w2 splits done — long since finished)
    cudaStreamWaitEvent(s0, eW2, 0);
    cudaStreamWaitEvent(s0, eM0, 0);
    gemm_f16_kernel<<<g0, 256, DYN_SMEM, s0>>>((const float*)p0[6], N0, 0, 2); // G2_0
    cudaEventRecord(eG20, s0);
    cudaStreamWaitEvent(s0, eM1, 0);
    gemm_f16_kernel<<<g1, 256, DYN_SMEM, s0>>>((const float*)p1[6], N1, 1, 3); // G2_1
    cudaEventRecord(eG21, s0);

    // s3: post0 under G2_1
    cudaStreamWaitEvent(s3, eG20, 0);
    post_kernel<<<(N0 + 7) / 8, 256, 0, s3>>>(f0, out0, 1, N0, 0);
    cudaEventRecord(ePost0, s3);

    // s2: post1 (tail)
    cudaStreamWaitEvent(s2, eG21, 0);
    post_kernel<<<(N1 + 7) / 8, 256, 0, s2>>>(f1, out1, 3, N1, 1);
    cudaEventRecord(ePost1, s2);

    // join
    cudaStreamWaitEvent(s0, ePost0, 0);
    cudaStreamWaitEvent(s0, ePost1, 0);
}